// round 1
// baseline (speedup 1.0000x reference)
#include <cuda_runtime.h>
#include <cstdint>

#define B_SZ   2048
#define T_SZ   60
#define F_SZ   89
#define H_SZ   1024
#define OUT_SZ 30
#define KTOT   (H_SZ + F_SZ)       // 1113: concat [h, x_t] along K
#define NCHUNK 70                  // ceil(1113/16) k-chunks of 16

// Persistent LSTM state (scratch via __device__ globals — no allocation).
__device__ float g_h0[B_SZ * H_SZ];
__device__ float g_h1[B_SZ * H_SZ];
__device__ float g_c [B_SZ * H_SZ];

__device__ __forceinline__ uint32_t f2tf(float v) {
    uint32_t u;
    asm("cvt.rna.tf32.f32 %0, %1;" : "=r"(u) : "f"(v));
    return u;
}

__device__ __forceinline__ void mma_tf32(float (&d)[4], const uint32_t (&a)[4],
                                         uint32_t b0, uint32_t b1) {
    asm volatile(
        "mma.sync.aligned.m16n8k8.row.col.f32.tf32.tf32.f32 "
        "{%0,%1,%2,%3}, {%4,%5,%6,%7}, {%8,%9}, {%0,%1,%2,%3};"
        : "+f"(d[0]), "+f"(d[1]), "+f"(d[2]), "+f"(d[3])
        : "r"(a[0]), "r"(a[1]), "r"(a[2]), "r"(a[3]), "r"(b0), "r"(b1));
}

__global__ void zero_state() {
    int n = B_SZ * H_SZ;
    for (int i = blockIdx.x * blockDim.x + threadIdx.x; i < n;
         i += gridDim.x * blockDim.x) {
        g_h0[i] = 0.f;
        g_c[i]  = 0.f;
    }
}

// One LSTM step:  z = [h_{t-1}, x_t] @ [[U],[W]] + b  (fused gates epilogue).
// CTA tile: 128 rows (batch) x 32 h-cols, computing all 4 gate strips
// (Ncat = 128 = 4 gates x 32) so the epilogue can combine i,f,g,o locally.
__global__ __launch_bounds__(256, 2)
void lstm_step(const float* __restrict__ x, const float* __restrict__ U,
               const float* __restrict__ W, const float* __restrict__ bias,
               int t) {
    const int m0 = blockIdx.x * 128;   // batch-row tile
    const int n0 = blockIdx.y * 32;    // h-col tile

    const float* __restrict__ hp = (t & 1) ? g_h1 : g_h0;
    float* __restrict__       hn = (t & 1) ? g_h0 : g_h1;

    __shared__ union {
        struct {
            uint32_t As[2][16][132];   // [buf][k][m]  (tf32 bits, +4 pad)
            uint32_t Bs[2][16][132];   // [buf][k][ncat]
        } ab;
        float zs[64][132];             // epilogue z staging (half tile)
    } sm;

    const int tid   = threadIdx.x;
    const int lane  = tid & 31;
    const int warp  = tid >> 5;
    const int warpM = warp >> 1;       // 0..3 -> 32-row slices
    const int warpN = warp & 1;        // 0..1 -> 64-col slices of Ncat=128

    float acc[2][8][4] = {};           // 32x64 per warp
    float aReg[8], bReg[8];

    auto loadA = [&](int c) {
#pragma unroll
        for (int j = 0; j < 8; j++) {
            int i  = tid + j * 256;
            int m  = i >> 4, kk = i & 15;
            int kg = c * 16 + kk;
            float v = 0.f;
            if (kg < H_SZ) {
                v = hp[(m0 + m) * H_SZ + kg];
            } else {
                int f = kg - H_SZ;
                if (f < F_SZ) v = x[((m0 + m) * T_SZ + t) * F_SZ + f];
            }
            aReg[j] = v;
        }
    };
    auto loadB = [&](int c) {
#pragma unroll
        for (int j = 0; j < 8; j++) {
            int i  = tid + j * 256;
            int kk = i >> 7, nc = i & 127;
            int g  = nc >> 5, nl = nc & 31;
            int n  = g * H_SZ + n0 + nl;    // gather the 4 gate strips
            int kg = c * 16 + kk;
            float v = 0.f;
            if (kg < H_SZ)      v = U[kg * (4 * H_SZ) + n];
            else if (kg < KTOT) v = W[(kg - H_SZ) * (4 * H_SZ) + n];
            bReg[j] = v;
        }
    };
    auto storeAB = [&](int buf) {
#pragma unroll
        for (int j = 0; j < 8; j++) {
            int i = tid + j * 256;
            sm.ab.As[buf][i & 15][i >> 4] = f2tf(aReg[j]);
        }
#pragma unroll
        for (int j = 0; j < 8; j++) {
            int i = tid + j * 256;
            sm.ab.Bs[buf][i >> 7][i & 127] = f2tf(bReg[j]);
        }
    };

    loadA(0); loadB(0); storeAB(0);
    __syncthreads();

    for (int c = 0; c < NCHUNK; c++) {
        const int cur = c & 1;
        if (c + 1 < NCHUNK) { loadA(c + 1); loadB(c + 1); }

#pragma unroll
        for (int kk2 = 0; kk2 < 2; kk2++) {
            const int kb = kk2 * 8 + (lane & 3);
            uint32_t af[2][4];
#pragma unroll
            for (int mi = 0; mi < 2; mi++) {
                int r = warpM * 32 + mi * 16 + (lane >> 2);
                af[mi][0] = sm.ab.As[cur][kb][r];
                af[mi][1] = sm.ab.As[cur][kb][r + 8];
                af[mi][2] = sm.ab.As[cur][kb + 4][r];
                af[mi][3] = sm.ab.As[cur][kb + 4][r + 8];
            }
#pragma unroll
            for (int ni = 0; ni < 8; ni++) {
                int cN = warpN * 64 + ni * 8 + (lane >> 2);
                uint32_t b0 = sm.ab.Bs[cur][kb][cN];
                uint32_t b1 = sm.ab.Bs[cur][kb + 4][cN];
#pragma unroll
                for (int mi = 0; mi < 2; mi++)
                    mma_tf32(acc[mi][ni], af[mi], b0, b1);
            }
        }

        if (c + 1 < NCHUNK) storeAB((c + 1) & 1);
        __syncthreads();
    }

    // ---- fused gate epilogue (two 64-row halves through shared) ----
#pragma unroll
    for (int half = 0; half < 2; half++) {
        if ((warpM >> 1) == half) {
#pragma unroll
            for (int mi = 0; mi < 2; mi++) {
                int zr = (warpM & 1) * 32 + mi * 16 + (lane >> 2);
#pragma unroll
                for (int ni = 0; ni < 8; ni++) {
                    int cN = warpN * 64 + ni * 8 + (lane & 3) * 2;
                    sm.zs[zr][cN]         = acc[mi][ni][0];
                    sm.zs[zr][cN + 1]     = acc[mi][ni][1];
                    sm.zs[zr + 8][cN]     = acc[mi][ni][2];
                    sm.zs[zr + 8][cN + 1] = acc[mi][ni][3];
                }
            }
        }
        __syncthreads();
#pragma unroll
        for (int e = 0; e < 8; e++) {
            int idx = tid + e * 256;          // 64*32 = 2048 elems
            int m  = idx >> 5, nl = idx & 31;
            int gm = m0 + half * 64 + m;
            int hc = n0 + nl;
            float zi = sm.zs[m][nl]      + bias[hc];
            float zf = sm.zs[m][32 + nl] + bias[H_SZ + hc];
            float zg = sm.zs[m][64 + nl] + bias[2 * H_SZ + hc];
            float zo = sm.zs[m][96 + nl] + bias[3 * H_SZ + hc];
            float ig = 1.f / (1.f + __expf(-zi));
            float fg = 1.f / (1.f + __expf(-zf));
            float gg = fmaxf(zg, 0.f);        // candidate activation = relu
            float og = 1.f / (1.f + __expf(-zo));
            int   ci = gm * H_SZ + hc;
            float cn = fg * g_c[ci] + ig * gg;
            g_c[ci] = cn;
            hn[ci]  = og * fmaxf(cn, 0.f);    // output activation = relu
        }
        __syncthreads();
    }
}

// y = h_T @ Wd + bd   ([2048,1024] x [1024,30]) — tiny, warp-reduce per output.
__global__ void head_kernel(const float* __restrict__ Wd,
                            const float* __restrict__ bd,
                            float* __restrict__ out) {
    __shared__ float hs[H_SZ];
    const int row  = blockIdx.x;
    const int tid  = threadIdx.x;
    const int lane = tid & 31;
    const int w    = tid >> 5;
    for (int i = tid; i < H_SZ; i += 256) hs[i] = g_h0[row * H_SZ + i];
    __syncthreads();
    for (int o = w; o < OUT_SZ; o += 8) {
        float s = 0.f;
        for (int k = lane; k < H_SZ; k += 32) s += hs[k] * Wd[k * OUT_SZ + o];
#pragma unroll
        for (int off = 16; off; off >>= 1)
            s += __shfl_down_sync(0xffffffffu, s, off);
        if (lane == 0) out[row * OUT_SZ + o] = s + bd[o];
    }
}

extern "C" void kernel_launch(void* const* d_in, const int* in_sizes, int n_in,
                              void* d_out, int out_size) {
    const float* x    = (const float*)d_in[0];   // [2048,60,89]
    const float* W    = (const float*)d_in[1];   // [89,4096]
    const float* U    = (const float*)d_in[2];   // [1024,4096]
    const float* bias = (const float*)d_in[3];   // [4096]
    const float* Wd   = (const float*)d_in[4];   // [1024,30]
    const float* bd   = (const float*)d_in[5];   // [30]
    float* out = (float*)d_out;                  // [2048,30,1]

    zero_state<<<1024, 256>>>();

    dim3 grid(B_SZ / 128, H_SZ / 32);            // 16 x 32 CTAs
    for (int t = 0; t < T_SZ; t++)
        lstm_step<<<grid, 256>>>(x, U, W, bias, t);

    head_kernel<<<B_SZ, 256>>>(Wd, bd, out);
}